// round 15
// baseline (speedup 1.0000x reference)
#include <cuda_runtime.h>
#include <cstdint>

#define Bn  32
#define En  512
#define Hn  512
#define Nn  50
#define Tn  100
#define VOn 31999
#define VOP 32000          // padded row count for transposed Wout
#define KSG 16             // gates k-splits
#define KCH 96             // 1536 / KSG

// smem layout for k_mega (bytes):
// [0, 131072)        : 4 quarters x 4-stage weight ring (8KB/stage)  | gates x-staging
// [131072, 204800)   : s_x  512*36 floats
#define SM_TILES 131072
#define SM_TOTAL 204800

// ---------------- scratch (device globals; referenced ONLY in device code) --
__device__ float g_emb[Bn * Tn * En];          // [B][T][E]
__device__ float g_featlin[Bn * Nn * Hn];      // [B][N][H]
__device__ float g_featemb[Bn * Nn * Hn];      // [B][N][H]
__device__ float g_h[Bn * Hn];
__device__ float g_c[Bn * Hn];
__device__ float g_voutb[2][Bn * Hn];          // double-buffered input_feat
__device__ float g_gp[KSG][Bn * 2048];         // gates partials
__device__ float g_WgT[1536 * 2048];           // [k][row], k = [vout|emb|h]
__device__ float g_WoutT[512 * VOP];           // [k][row], col 31999 zero
__device__ float g_WhT[3 * 512 * 512];         // [mat][k][row]: Wlh,Weh,Wlo
__device__ unsigned long long g_amax[Bn * Tn];

// ---------------- f32x2 packed-FMA helpers (sm_103a) ------------------------
__device__ __forceinline__ void fma2(unsigned long long& d,
                                     unsigned long long a, unsigned long long b) {
    asm("fma.rn.f32x2 %0, %1, %2, %0;" : "+l"(d) : "l"(a), "l"(b));
}
__device__ __forceinline__ unsigned long long packf2(float a, float b) {
    unsigned long long r;
    asm("mov.b64 %0, {%1, %2};" : "=l"(r) : "f"(a), "f"(b));
    return r;
}
__device__ __forceinline__ float2 u2f2(unsigned long long v) {
    float2 r;
    asm("mov.b64 {%0, %1}, %2;" : "=f"(r.x), "=f"(r.y) : "l"(v));
    return r;
}

// ---------------- cp.async helpers ------------------------------------------
__device__ __forceinline__ void cp_async16(uint32_t smem_dst, const float* gsrc) {
    asm volatile("cp.async.cg.shared.global [%0], [%1], 16;"
                 :: "r"(smem_dst), "l"(gsrc));
}
__device__ __forceinline__ void cp_commit() {
    asm volatile("cp.async.commit_group;" ::: "memory");
}
__device__ __forceinline__ void cp_wait2() {
    asm volatile("cp.async.wait_group 2;" ::: "memory");
}

// issue one 8KB weight stage (8 k-rows x 256 rows) for quarter kq
__device__ __forceinline__ void issue_stage(int s, uint32_t s_tile, int k_base,
                                            int rowb, int j0, int rr0) {
    uint32_t dst = s_tile + ((uint32_t)(s & 3)) * 8192u;
    const float* p0 = g_WoutT + (size_t)(k_base + s * 8 + j0) * VOP + rowb + rr0;
    const float* p1 = g_WoutT + (size_t)(k_base + s * 8 + j0 + 4) * VOP + rowb + rr0;
    cp_async16(dst + (uint32_t)(j0 * 1024 + rr0 * 4), p0);
    cp_async16(dst + (uint32_t)((j0 + 4) * 1024 + rr0 * 4), p1);
}

// ---------------- merged init + embedding gather ------------------------------
__global__ void k_setup(const float* __restrict__ feats,
                        const int* __restrict__ captions,
                        const float* __restrict__ table) {
    int blk = blockIdx.x;
    if (blk < 6400) {
        int i = blk * 256 + threadIdx.x;               // Bn*Tn*En
        int bt = i / En, e = i % En;
        g_emb[i] = table[(size_t)captions[bt] * En + e];
    } else {
        int i = (blk - 6400) * 256 + threadIdx.x;      // 0..16383
        int b = i / En, e = i % En;
        const float* p = feats + ((size_t)b * En + e) * Nn;
        float s = 0.f;
        #pragma unroll
        for (int n = 0; n < Nn; n++) s += p[n];
        float avg = s * (1.0f / Nn);
        g_voutb[0][i] = avg;
        g_voutb[1][i] = avg;
        g_h[i] = 0.f;
        g_c[i] = 0.f;
        if (i < Bn * Tn) g_amax[i] = 0ull;
    }
}

// ---------------- merged weight transposes (once per replay) ------------------
__global__ void k_tr(const float* __restrict__ Wout,
                     const float* __restrict__ W_ih, const float* __restrict__ W_hh,
                     const float* __restrict__ Wlh, const float* __restrict__ Weh,
                     const float* __restrict__ Wlo) {
    __shared__ float tile[32][33];
    int tx = threadIdx.x, ty = threadIdx.y;            // 32 x 8
    int blk = blockIdx.x;
    if (blk < 16000) {
        int rb = (blk % 1000) * 32;                    // vocab rows
        int kb = (blk / 1000) * 32;                    // k
        #pragma unroll
        for (int j = 0; j < 32; j += 8) {
            int r = rb + ty + j;
            tile[ty + j][tx] = (r < VOn) ? Wout[(size_t)r * 512 + kb + tx] : 0.f;
        }
        __syncthreads();
        #pragma unroll
        for (int j = 0; j < 32; j += 8)
            g_WoutT[(size_t)(kb + ty + j) * VOP + rb + tx] = tile[tx][ty + j];
    } else if (blk < 19072) {
        blk -= 16000;
        int rb = (blk % 64) * 32;                      // gate rows
        int kb = (blk / 64) * 32;                      // k
        #pragma unroll
        for (int j = 0; j < 32; j += 8) {
            int row = rb + ty + j, k = kb + tx;
            tile[ty + j][tx] = (k < 1024) ? W_ih[(size_t)row * 1024 + k]
                                          : W_hh[(size_t)row * 512 + (k - 1024)];
        }
        __syncthreads();
        #pragma unroll
        for (int j = 0; j < 32; j += 8)
            g_WgT[(size_t)(kb + ty + j) * 2048 + rb + tx] = tile[tx][ty + j];
    } else {
        int m = blk - 19072;                           // 0..767
        int mat = m >> 8;                              // 0..2
        int mm = m & 255;
        int rb = (mm & 15) * 32;
        int kb = (mm >> 4) * 32;
        const float* src = (mat == 0) ? Wlh : (mat == 1) ? Weh : Wlo;
        #pragma unroll
        for (int j = 0; j < 32; j += 8)
            tile[ty + j][tx] = src[(size_t)(rb + ty + j) * 512 + kb + tx];
        __syncthreads();
        #pragma unroll
        for (int j = 0; j < 32; j += 8)
            g_WhT[(size_t)mat * 262144 + (size_t)(kb + ty + j) * 512 + rb + tx]
                = tile[tx][ty + j];
    }
}

// ---------------- feature projections (setup only) ---------------------------
__global__ void k_proj(const float* __restrict__ W, const float* __restrict__ bias,
                       const float* __restrict__ Xext, int which) {
    __shared__ float s_f[64 * 52];
    int b = blockIdx.x;
    int hbase = blockIdx.y * 64;
    int hl = threadIdx.x >> 2;
    int ng = threadIdx.x & 3;
    const float* X = which ? g_featlin : Xext;
    float* Y = which ? g_featemb : g_featlin;
    int se = which ? 1 : Nn;
    int sn = which ? Hn : 1;
    const float* Xb = X + (size_t)b * En * Nn;

    float acc[13];
    #pragma unroll
    for (int q = 0; q < 13; q++) acc[q] = 0.f;

    for (int et = 0; et < En / 64; et++) {
        __syncthreads();
        for (int i = threadIdx.x; i < 64 * Nn; i += 256) {
            int e, n;
            if (which == 0) { e = i / Nn; n = i % Nn; }
            else            { e = i & 63; n = i >> 6; }
            s_f[e * 52 + n] = Xb[(size_t)(et * 64 + e) * se + (size_t)n * sn];
        }
        __syncthreads();
        #pragma unroll 4
        for (int e = 0; e < 64; e++) {
            float w = W[(size_t)(hbase + hl) * En + et * 64 + e];
            #pragma unroll
            for (int q = 0; q < 13; q++)
                acc[q] += w * s_f[e * 52 + ng + 4 * q];
        }
    }
    float bv = bias[hbase + hl];
    #pragma unroll
    for (int q = 0; q < 13; q++) {
        int n = ng + 4 * q;
        if (n < Nn) {
            float v = acc[q] + bv;
            if (which == 0) v = fmaxf(v, 0.f);
            Y[((size_t)b * Nn + n) * Hn + hbase + hl] = v;
        }
    }
}

// ================= MEGA kernel: logits(t-1) + gates(t) =======================
// blocks [0,125): logits (1024 thr, k-split 4, cp.async ring-4 weight tiles)
// blocks [125,157): gates partials, four 256-thread units per block
__global__ __launch_bounds__(1024) void k_mega(const float* __restrict__ bout,
                                               float* __restrict__ out,
                                               int t, int gates_on) {
    extern __shared__ char smc[];
    __shared__ unsigned long long s_bmax[32];
    int tid = threadIdx.x, lane = tid & 31;
    int kq = tid >> 8, rtid = tid & 255;

    if (blockIdx.x < 125) {
        // ---------------- logits role: step lt = t-1 -------------------------
        int lt = t - 1;
        if (lt < 0) return;
        int buf = lt & 1;
        float* s_x = (float*)(smc + SM_TILES);
        uint32_t sbase = (uint32_t)__cvta_generic_to_shared(smc);
        uint32_t s_tile = sbase + (uint32_t)kq * 32768u;   // 4 bufs x 8KB
        int k_base = kq * 128;
        int rowb = blockIdx.x * 256;
        int j0 = rtid >> 6;                 // 0..3
        int rr0 = (rtid & 63) * 4;          // 0..252

        if (tid < 32) s_bmax[tid] = 0ull;
        for (int idx = tid; idx < 512 * Bn; idx += 1024) {
            int b = idx >> 9, k = idx & 511;
            s_x[k * 36 + b] = g_voutb[buf][b * Hn + k];
        }
        __syncthreads();

        issue_stage(0, s_tile, k_base, rowb, j0, rr0); cp_commit();
        issue_stage(1, s_tile, k_base, rowb, j0, rr0); cp_commit();
        issue_stage(2, s_tile, k_base, rowb, j0, rr0); cp_commit();

        unsigned long long acc[16];
        #pragma unroll
        for (int i = 0; i < 16; i++) acc[i] = 0ull;

        int barid = 1 + kq;
        #pragma unroll 1
        for (int s = 0; s < 16; s++) {
            cp_wait2();
            asm volatile("bar.sync %0, 256;" :: "r"(barid) : "memory");
            if (s + 3 < 16)
                issue_stage(s + 3, s_tile, k_base, rowb, j0, rr0);
            cp_commit();
            const float* wt = (const float*)(smc + kq * 32768 + (s & 3) * 8192);
            const float* xs = s_x + (size_t)(k_base + s * 8) * 36;
            #pragma unroll
            for (int j = 0; j < 8; j++) {
                float w = wt[j * 256 + rtid];
                unsigned long long w2 = packf2(w, w);
                const ulonglong2* x2 = (const ulonglong2*)(xs + j * 36);
                #pragma unroll
                for (int q = 0; q < 8; q++) {
                    ulonglong2 xv = x2[q];
                    fma2(acc[2 * q], w2, xv.x);
                    fma2(acc[2 * q + 1], w2, xv.y);
                }
            }
        }

        // combine quarters (fixed order -> deterministic); reuse tile area
        __syncthreads();
        float* red = (float*)smc;                      // stride-33 layout
        if (kq) {
            float* dst = red + (size_t)(kq - 1) * 8448 + rtid * 33;
            #pragma unroll
            for (int a = 0; a < 16; a++) {
                float2 f = u2f2(acc[a]);
                dst[2 * a]     = f.x;
                dst[2 * a + 1] = f.y;
            }
        }
        __syncthreads();

        if (kq == 0) {
            const float* r1 = red + rtid * 33;
            const float* r2 = red + 8448 + rtid * 33;
            const float* r3 = red + 16896 + rtid * 33;
            int r = rowb + rtid;
            bool ok = r < VOn;
            float bo = ok ? bout[r] : 0.f;
            #pragma unroll
            for (int a = 0; a < 16; a++) {
                float2 f = u2f2(acc[a]);
                #pragma unroll
                for (int hh = 0; hh < 2; hh++) {
                    int b = 2 * a + hh;
                    float s = (hh ? f.y : f.x) + r1[b] + r2[b] + r3[b] + bo;
                    unsigned long long key = 0ull;
                    if (ok) {
                        // streaming store: keep logits out of L2 so WoutT stays
                        __stcs(&out[((size_t)b * Tn + lt) * VOn + r], s);
                        unsigned u = __float_as_uint(s);
                        unsigned hi = (u & 0x80000000u) ? ~u : (u | 0x80000000u);
                        key = ((unsigned long long)hi << 32)
                            | (unsigned long long)(0x7FFFFFFFu - (unsigned)r);
                    }
                    #pragma unroll
                    for (int off = 16; off; off >>= 1) {
                        unsigned long long o2 = __shfl_xor_sync(0xffffffffu, key, off);
                        if (o2 > key) key = o2;
                    }
                    if (lane == 0) atomicMax(&s_bmax[b], key);
                }
            }
        }
        __syncthreads();
        if (tid < 32)
            atomicMax(&g_amax[tid * Tn + lt], s_bmax[tid]);
    } else {
        // ---------------- gates role: step t, four 256-thr units -------------
        if (!gates_on) return;
        int vb = (blockIdx.x - 125) * 4 + kq;          // 0..127
        int rb = vb & 7, ks = vb >> 3;
        int row = rb * 256 + rtid;
        int buf = (t + 1) & 1;                         // vout produced at t-1
        float* s_x = (float*)(smc + kq * (KCH * 36 * 4));

        for (int idx = rtid; idx < KCH * Bn; idx += 256) {
            int b = idx / KCH, i = idx - b * KCH;
            int kg = ks * KCH + i;
            float v;
            if (kg < 512)       v = g_voutb[buf][b * Hn + kg];
            else if (kg < 1024) v = g_emb[((size_t)b * Tn + t) * En + (kg - 512)];
            else                v = g_h[b * Hn + (kg - 1024)];
            s_x[i * 36 + b] = v;
        }
        __syncthreads();

        unsigned long long acc[16];
        #pragma unroll
        for (int i = 0; i < 16; i++) acc[i] = 0ull;

        const float* Wc = g_WgT + (size_t)(ks * KCH) * 2048 + row;

        float wreg[8];
        #pragma unroll
        for (int j = 0; j < 8; j++) wreg[j] = Wc[(size_t)j * 2048];

        #pragma unroll 1
        for (int i0 = 0; i0 < KCH; i0 += 8) {
            float wcur[8];
            #pragma unroll
            for (int j = 0; j < 8; j++) wcur[j] = wreg[j];
            if (i0 + 8 < KCH) {
                #pragma unroll
                for (int j = 0; j < 8; j++) wreg[j] = Wc[(size_t)(i0 + 8 + j) * 2048];
            }
            #pragma unroll
            for (int j = 0; j < 8; j++) {
                unsigned long long w2 = packf2(wcur[j], wcur[j]);
                const ulonglong2* x2 = (const ulonglong2*)&s_x[(i0 + j) * 36];
                #pragma unroll
                for (int q = 0; q < 8; q++) {
                    ulonglong2 xv = x2[q];
                    fma2(acc[2 * q], w2, xv.x);
                    fma2(acc[2 * q + 1], w2, xv.y);
                }
            }
        }
        float* gp = &g_gp[ks][row];
        #pragma unroll
        for (int a = 0; a < 16; a++) {
            float2 f = u2f2(acc[a]);
            gp[(size_t)(2 * a) * 2048]     = f.x;
            gp[(size_t)(2 * a + 1) * 2048] = f.y;
        }
    }
}

// ---------------- transposed-weight GEMV (1024 threads, k-streaming) ---------
__device__ __forceinline__ void gemvT512(const float* __restrict__ WT,
                                         const float* __restrict__ bias,
                                         const float* __restrict__ s_x,
                                         float* __restrict__ s_red,
                                         float* __restrict__ s_out,
                                         int tid, int dotanh) {
    int rp = tid & 255;                 // row pair: rows 2rp, 2rp+1
    int kq = tid >> 8;                  // k quarter: 0..3
    const float2* Wc = (const float2*)WT + (size_t)(kq * 128) * 256 + rp;
    const float* xq = s_x + kq * 128;
    unsigned long long acc = 0ull;

    float2 wreg[8];
    #pragma unroll
    for (int j = 0; j < 8; j++) wreg[j] = Wc[(size_t)j * 256];

    #pragma unroll 1
    for (int i0 = 0; i0 < 128; i0 += 8) {
        float2 wcur[8];
        #pragma unroll
        for (int j = 0; j < 8; j++) wcur[j] = wreg[j];
        if (i0 + 8 < 128) {
            #pragma unroll
            for (int j = 0; j < 8; j++) wreg[j] = Wc[(size_t)(i0 + 8 + j) * 256];
        }
        #pragma unroll
        for (int j = 0; j < 8; j++) {
            float xv = xq[i0 + j];
            fma2(acc, packf2(wcur[j].x, wcur[j].y), packf2(xv, xv));
        }
    }

    float2 f = u2f2(acc);
    if (kq) {
        s_red[(kq - 1) * 512 + 2 * rp]     = f.x;
        s_red[(kq - 1) * 512 + 2 * rp + 1] = f.y;
    }
    __syncthreads();
    if (kq == 0) {
        float y0 = f.x + s_red[2 * rp]     + s_red[512 + 2 * rp]
                       + s_red[1024 + 2 * rp]     + bias[2 * rp];
        float y1 = f.y + s_red[2 * rp + 1] + s_red[512 + 2 * rp + 1]
                       + s_red[1024 + 2 * rp + 1] + bias[2 * rp + 1];
        if (dotanh) { y0 = tanhf(y0); y1 = tanhf(y1); }
        *(float2*)&s_out[2 * rp] = make_float2(y0, y1);
    }
    __syncthreads();
}

// ---------------- fused LSTM-reduce + hidden chain + attention + vout --------
__global__ __launch_bounds__(1024) void k_hidden_attn(
        const float* __restrict__ b_ih, const float* __restrict__ b_hh,
        const float* __restrict__ blh, const float* __restrict__ beh,
        const float* __restrict__ Wa,  const float* __restrict__ ba,
        const float* __restrict__ blo, int t) {
    __shared__ __align__(16) float s_h[512];
    __shared__ __align__(16) float s_hl[512];
    __shared__ __align__(16) float s_he[512];
    __shared__ __align__(16) float s_v[512];
    __shared__ __align__(16) float s_red[3 * 512];
    __shared__ float s_sc[64], s_att[64];
    int b = blockIdx.x, tid = threadIdx.x, w = tid >> 5, lane = tid & 31;
    int obuf = t & 1;                          // vout buffer written this step

    if (tid < 512) {
        int u = tid;
        float gi = b_ih[u]        + b_hh[u];
        float gf = b_ih[512 + u]  + b_hh[512 + u];
        float gg = b_ih[1024 + u] + b_hh[1024 + u];
        float go = b_ih[1536 + u] + b_hh[1536 + u];
        #pragma unroll
        for (int ks = 0; ks < KSG; ks++) {
            const float* gp = &g_gp[ks][b * 2048];
            gi += gp[u];
            gf += gp[512 + u];
            gg += gp[1024 + u];
            go += gp[1536 + u];
        }
        float si = 1.f / (1.f + expf(-gi));
        float sf = 1.f / (1.f + expf(-gf));
        float so = 1.f / (1.f + expf(-go));
        int idx = b * Hn + u;
        float c = sf * g_c[idx] + si * tanhf(gg);
        g_c[idx] = c;
        float h = so * tanhf(c);
        s_h[u] = h;
        g_h[idx] = h;
    }
    __syncthreads();

    gemvT512(g_WhT,          blh, s_h,  s_red, s_hl, tid, 1);   // linear_hidden
    gemvT512(g_WhT + 262144, beh, s_hl, s_red, s_he, tid, 0);   // embed_hidden

    for (int n = w; n < Nn; n += 32) {
        const float* fe = g_featemb + ((size_t)b * Nn + n) * Hn;
        float p = 0.f;
        #pragma unroll 8
        for (int h = lane; h < Hn; h += 32)
            p += Wa[h] * tanhf(fe[h] + s_he[h]);
        #pragma unroll
        for (int off = 16; off; off >>= 1) p += __shfl_xor_sync(0xffffffffu, p, off);
        if (lane == 0) s_sc[n] = p + ba[0];
    }
    __syncthreads();

    if (w == 0) {
        float v0 = (lane < Nn) ? s_sc[lane] : -1e30f;
        float v1 = (lane + 32 < Nn) ? s_sc[lane + 32] : -1e30f;
        float m = fmaxf(v0, v1);
        #pragma unroll
        for (int off = 16; off; off >>= 1) m = fmaxf(m, __shfl_xor_sync(0xffffffffu, m, off));
        float e0 = (lane < Nn) ? expf(v0 - m) : 0.f;
        float e1 = (lane + 32 < Nn) ? expf(v1 - m) : 0.f;
        float s = e0 + e1;
        #pragma unroll
        for (int off = 16; off; off >>= 1) s += __shfl_xor_sync(0xffffffffu, s, off);
        float inv = 1.f / s;
        if (lane < Nn) s_att[lane] = e0 * inv;
        if (lane + 32 < Nn) s_att[lane + 32] = e1 * inv;
    }
    __syncthreads();

    if (tid < 512) {
        int h = tid;
        float acc = s_hl[h];
        const float* fl = g_featlin + (size_t)b * Nn * Hn + h;
        #pragma unroll 10
        for (int n = 0; n < Nn; n++)
            acc += s_att[n] * fl[(size_t)n * Hn];
        s_v[h] = acc;
    }
    __syncthreads();

    gemvT512(g_WhT + 2 * 262144, blo, s_v, s_red,
             &g_voutb[obuf][b * Hn], tid, 1);                   // linear_out
}

// ---------------- convert argmax keys to float ids ---------------------------
__global__ void k_final(float* __restrict__ out_ids) {
    int i = blockIdx.x * blockDim.x + threadIdx.x;
    if (i >= Bn * Tn) return;
    unsigned long long key = g_amax[i];
    unsigned r = 0x7FFFFFFFu - (unsigned)(key & 0xFFFFFFFFull);
    out_ids[i] = (float)r;
}

// ---------------- launch ------------------------------------------------------
extern "C" void kernel_launch(void* const* d_in, const int* in_sizes, int n_in,
                              void* d_out, int out_size) {
    const float* features = (const float*)d_in[0];
    // d_in[1] = mask (unused)
    const int*   captions = (const int*)d_in[2];
    const float* table    = (const float*)d_in[3];
    const float* W_ih = (const float*)d_in[4];
    const float* b_ih = (const float*)d_in[5];
    const float* W_hh = (const float*)d_in[6];
    const float* b_hh = (const float*)d_in[7];
    const float* Wf  = (const float*)d_in[8];
    const float* bf  = (const float*)d_in[9];
    const float* We  = (const float*)d_in[10];
    const float* be  = (const float*)d_in[11];
    const float* Wlh = (const float*)d_in[12];
    const float* blh = (const float*)d_in[13];
    const float* Weh = (const float*)d_in[14];
    const float* beh = (const float*)d_in[15];
    const float* Wa  = (const float*)d_in[16];
    const float* ba  = (const float*)d_in[17];
    const float* Wlo = (const float*)d_in[18];
    const float* blo = (const float*)d_in[19];
    const float* Wout = (const float*)d_in[20];
    const float* bout = (const float*)d_in[21];
    float* out = (float*)d_out;

    cudaFuncSetAttribute(k_mega, cudaFuncAttributeMaxDynamicSharedMemorySize, SM_TOTAL);

    k_setup<<<6464, 256>>>(features, captions, table);
    k_tr<<<19840, dim3(32, 8)>>>(Wout, W_ih, W_hh, Wlh, Weh, Wlo);
    k_proj<<<dim3(Bn, Hn / 64), 256>>>(Wf, bf, features, 0);
    k_proj<<<dim3(Bn, Hn / 64), 256>>>(We, be, features, 1);

    for (int t = 0; t < Tn; t++) {
        k_mega<<<157, 1024, SM_TOTAL>>>(bout, out, t, 1);  // logits(t-1)+gates(t)
        k_hidden_attn<<<Bn, 1024>>>(b_ih, b_hh, blh, beh, Wa, ba, blo, t);
    }
    k_mega<<<157, 1024, SM_TOTAL>>>(bout, out, Tn, 0);     // final logits(99)

    float* ids = out + ((size_t)out_size - (size_t)Bn * Tn);
    k_final<<<(Bn * Tn + 255) / 256, 256>>>(ids);
}

// round 16
// speedup vs baseline: 1.1862x; 1.1862x over previous
#include <cuda_runtime.h>
#include <cstdint>

#define Bn  32
#define En  512
#define Hn  512
#define Nn  50
#define Tn  100
#define VOn 31999
#define VOP 32000          // padded row count for transposed Wout
#define KSG 16             // gates k-splits
#define KCH 96             // 1536 / KSG

#define SM_DYN 73728       // dynamic smem for k_hidlog: s_x 512*36 floats

// ---------------- scratch (device globals; referenced ONLY in device code) --
__device__ float g_emb[Bn * Tn * En];          // [B][T][E]
__device__ float g_featlin[Bn * Nn * Hn];      // [B][N][H]
__device__ float g_featemb[Bn * Nn * Hn];      // [B][N][H]
__device__ float g_h[Bn * Hn];
__device__ float g_c[Bn * Hn];
__device__ float g_voutb[2][Bn * Hn];          // double-buffered input_feat
__device__ float g_gp[KSG][Bn * 2048];         // gates partials
__device__ float g_WgT[1536 * 2048];           // [k][row], k = [vout|emb|h]
__device__ float g_WoutT[512 * VOP];           // [k][row], col 31999 zero
__device__ float g_WhT[3 * 512 * 512];         // [mat][k][row]: Wlh,Weh,Wlo
__device__ unsigned long long g_amax[Bn * Tn];

// ---------------- f32x2 packed-FMA helpers (sm_103a) ------------------------
__device__ __forceinline__ void fma2(unsigned long long& d,
                                     unsigned long long a, unsigned long long b) {
    asm("fma.rn.f32x2 %0, %1, %2, %0;" : "+l"(d) : "l"(a), "l"(b));
}
__device__ __forceinline__ unsigned long long packf2(float a, float b) {
    unsigned long long r;
    asm("mov.b64 %0, {%1, %2};" : "=l"(r) : "f"(a), "f"(b));
    return r;
}
__device__ __forceinline__ float2 u2f2(unsigned long long v) {
    float2 r;
    asm("mov.b64 {%0, %1}, %2;" : "=f"(r.x), "=f"(r.y) : "l"(v));
    return r;
}

// ---------------- merged init + embedding gather ------------------------------
__global__ void k_setup(const float* __restrict__ feats,
                        const int* __restrict__ captions,
                        const float* __restrict__ table) {
    int blk = blockIdx.x;
    if (blk < 6400) {
        int i = blk * 256 + threadIdx.x;               // Bn*Tn*En
        int bt = i / En, e = i % En;
        g_emb[i] = table[(size_t)captions[bt] * En + e];
    } else {
        int i = (blk - 6400) * 256 + threadIdx.x;      // 0..16383
        int b = i / En, e = i % En;
        const float* p = feats + ((size_t)b * En + e) * Nn;
        float s = 0.f;
        #pragma unroll
        for (int n = 0; n < Nn; n++) s += p[n];
        float avg = s * (1.0f / Nn);
        g_voutb[0][i] = avg;
        g_voutb[1][i] = avg;
        g_h[i] = 0.f;
        g_c[i] = 0.f;
        if (i < Bn * Tn) g_amax[i] = 0ull;
    }
}

// ---------------- merged weight transposes (once per replay) ------------------
__global__ void k_tr(const float* __restrict__ Wout,
                     const float* __restrict__ W_ih, const float* __restrict__ W_hh,
                     const float* __restrict__ Wlh, const float* __restrict__ Weh,
                     const float* __restrict__ Wlo) {
    __shared__ float tile[32][33];
    int tx = threadIdx.x, ty = threadIdx.y;            // 32 x 8
    int blk = blockIdx.x;
    if (blk < 16000) {
        int rb = (blk % 1000) * 32;                    // vocab rows
        int kb = (blk / 1000) * 32;                    // k
        #pragma unroll
        for (int j = 0; j < 32; j += 8) {
            int r = rb + ty + j;
            tile[ty + j][tx] = (r < VOn) ? Wout[(size_t)r * 512 + kb + tx] : 0.f;
        }
        __syncthreads();
        #pragma unroll
        for (int j = 0; j < 32; j += 8)
            g_WoutT[(size_t)(kb + ty + j) * VOP + rb + tx] = tile[tx][ty + j];
    } else if (blk < 19072) {
        blk -= 16000;
        int rb = (blk % 64) * 32;                      // gate rows
        int kb = (blk / 64) * 32;                      // k
        #pragma unroll
        for (int j = 0; j < 32; j += 8) {
            int row = rb + ty + j, k = kb + tx;
            tile[ty + j][tx] = (k < 1024) ? W_ih[(size_t)row * 1024 + k]
                                          : W_hh[(size_t)row * 512 + (k - 1024)];
        }
        __syncthreads();
        #pragma unroll
        for (int j = 0; j < 32; j += 8)
            g_WgT[(size_t)(kb + ty + j) * 2048 + rb + tx] = tile[tx][ty + j];
    } else {
        int m = blk - 19072;                           // 0..767
        int mat = m >> 8;                              // 0..2
        int mm = m & 255;
        int rb = (mm & 15) * 32;
        int kb = (mm >> 4) * 32;
        const float* src = (mat == 0) ? Wlh : (mat == 1) ? Weh : Wlo;
        #pragma unroll
        for (int j = 0; j < 32; j += 8)
            tile[ty + j][tx] = src[(size_t)(rb + ty + j) * 512 + kb + tx];
        __syncthreads();
        #pragma unroll
        for (int j = 0; j < 32; j += 8)
            g_WhT[(size_t)mat * 262144 + (size_t)(kb + ty + j) * 512 + rb + tx]
                = tile[tx][ty + j];
    }
}

// ---------------- feature projections (setup only) ---------------------------
__global__ void k_proj(const float* __restrict__ W, const float* __restrict__ bias,
                       const float* __restrict__ Xext, int which) {
    __shared__ float s_f[64 * 52];
    int b = blockIdx.x;
    int hbase = blockIdx.y * 64;
    int hl = threadIdx.x >> 2;
    int ng = threadIdx.x & 3;
    const float* X = which ? g_featlin : Xext;
    float* Y = which ? g_featemb : g_featlin;
    int se = which ? 1 : Nn;
    int sn = which ? Hn : 1;
    const float* Xb = X + (size_t)b * En * Nn;

    float acc[13];
    #pragma unroll
    for (int q = 0; q < 13; q++) acc[q] = 0.f;

    for (int et = 0; et < En / 64; et++) {
        __syncthreads();
        for (int i = threadIdx.x; i < 64 * Nn; i += 256) {
            int e, n;
            if (which == 0) { e = i / Nn; n = i % Nn; }
            else            { e = i & 63; n = i >> 6; }
            s_f[e * 52 + n] = Xb[(size_t)(et * 64 + e) * se + (size_t)n * sn];
        }
        __syncthreads();
        #pragma unroll 4
        for (int e = 0; e < 64; e++) {
            float w = W[(size_t)(hbase + hl) * En + et * 64 + e];
            #pragma unroll
            for (int q = 0; q < 13; q++)
                acc[q] += w * s_f[e * 52 + ng + 4 * q];
        }
    }
    float bv = bias[hbase + hl];
    #pragma unroll
    for (int q = 0; q < 13; q++) {
        int n = ng + 4 * q;
        if (n < Nn) {
            float v = acc[q] + bv;
            if (which == 0) v = fmaxf(v, 0.f);
            Y[((size_t)b * Nn + n) * Hn + hbase + hl] = v;
        }
    }
}

// ---------------- gates partial GEMM (standalone; R12-proven shape) ----------
// grid 128: rb = blk&7 (row block of 256), ks = blk>>3 (k chunk of 96)
__global__ __launch_bounds__(256) void k_gates(int t) {
    __shared__ __align__(16) float s_x[KCH * 36];
    int rb = blockIdx.x & 7, ks = blockIdx.x >> 3;
    int tid = threadIdx.x;
    int row = rb * 256 + tid;
    int buf = (t + 1) & 1;                     // vout produced at step t-1

    for (int idx = tid; idx < KCH * Bn; idx += 256) {
        int b = idx / KCH, i = idx - b * KCH;
        int kg = ks * KCH + i;
        float v;
        if (kg < 512)       v = g_voutb[buf][b * Hn + kg];
        else if (kg < 1024) v = g_emb[((size_t)b * Tn + t) * En + (kg - 512)];
        else                v = g_h[b * Hn + (kg - 1024)];
        s_x[i * 36 + b] = v;
    }
    __syncthreads();

    unsigned long long acc[16];
    #pragma unroll
    for (int i = 0; i < 16; i++) acc[i] = 0ull;

    const float* Wc = g_WgT + (size_t)(ks * KCH) * 2048 + row;

    float wreg[8];
    #pragma unroll
    for (int j = 0; j < 8; j++) wreg[j] = Wc[(size_t)j * 2048];

    #pragma unroll 1
    for (int i0 = 0; i0 < KCH; i0 += 8) {
        float wcur[8];
        #pragma unroll
        for (int j = 0; j < 8; j++) wcur[j] = wreg[j];
        if (i0 + 8 < KCH) {
            #pragma unroll
            for (int j = 0; j < 8; j++) wreg[j] = Wc[(size_t)(i0 + 8 + j) * 2048];
        }
        #pragma unroll
        for (int j = 0; j < 8; j++) {
            unsigned long long w2 = packf2(wcur[j], wcur[j]);
            const ulonglong2* x2 = (const ulonglong2*)&s_x[(i0 + j) * 36];
            #pragma unroll
            for (int q = 0; q < 8; q++) {
                ulonglong2 xv = x2[q];
                fma2(acc[2 * q], w2, xv.x);
                fma2(acc[2 * q + 1], w2, xv.y);
            }
        }
    }
    float* gp = &g_gp[ks][row];
    #pragma unroll
    for (int a = 0; a < 16; a++) {
        float2 f = u2f2(acc[a]);
        gp[(size_t)(2 * a) * 2048]     = f.x;
        gp[(size_t)(2 * a + 1) * 2048] = f.y;
    }
}

// ---------------- 512-thread GEMV (k-halves, 4 acc chains) -------------------
// y[512] = W[512x512]^T-layout @ x[512]. Deterministic fixed-order combine.
__device__ __forceinline__ void gemv512_h(const float* __restrict__ WT,
                                          const float* __restrict__ bias,
                                          const float* __restrict__ s_x,
                                          float* __restrict__ s_red,
                                          float* __restrict__ s_out,
                                          int tid, int dotanh) {
    int rp = tid & 255;                 // row pair: rows 2rp, 2rp+1
    int kh = tid >> 8;                  // k half: 0..1 (256 k each)
    const float2* Wc = (const float2*)WT + (size_t)(kh * 256) * 256 + rp;
    const float* xq = s_x + kh * 256;
    unsigned long long acc[4];
    #pragma unroll
    for (int i = 0; i < 4; i++) acc[i] = 0ull;

    float2 wreg[8];
    #pragma unroll
    for (int j = 0; j < 8; j++) wreg[j] = Wc[(size_t)j * 256];

    #pragma unroll 1
    for (int i0 = 0; i0 < 256; i0 += 8) {
        float2 wcur[8];
        #pragma unroll
        for (int j = 0; j < 8; j++) wcur[j] = wreg[j];
        if (i0 + 8 < 256) {
            #pragma unroll
            for (int j = 0; j < 8; j++) wreg[j] = Wc[(size_t)(i0 + 8 + j) * 256];
        }
        #pragma unroll
        for (int j = 0; j < 8; j++) {
            float xv = xq[i0 + j];
            fma2(acc[j & 3], packf2(wcur[j].x, wcur[j].y), packf2(xv, xv));
        }
    }
    float2 f0 = u2f2(acc[0]), f1 = u2f2(acc[1]);
    float2 f2 = u2f2(acc[2]), f3 = u2f2(acc[3]);
    float fx = ((f0.x + f1.x) + f2.x) + f3.x;
    float fy = ((f0.y + f1.y) + f2.y) + f3.y;

    if (kh) {
        s_red[2 * rp]     = fx;
        s_red[2 * rp + 1] = fy;
    }
    __syncthreads();
    if (kh == 0) {
        float y0 = fx + s_red[2 * rp]     + bias[2 * rp];
        float y1 = fy + s_red[2 * rp + 1] + bias[2 * rp + 1];
        if (dotanh) { y0 = tanhf(y0); y1 = tanhf(y1); }
        *(float2*)&s_out[2 * rp] = make_float2(y0, y1);
    }
    __syncthreads();
}

// ================= HIDLOG kernel: hidden(t) + logits(t-1) ====================
// blocks [0,32): hidden (one per batch); blocks [32,282): logits, 128 rows each
__global__ __launch_bounds__(512, 2) void k_hidlog(
        const float* __restrict__ bout, float* __restrict__ out,
        const float* __restrict__ b_ih, const float* __restrict__ b_hh,
        const float* __restrict__ blh, const float* __restrict__ beh,
        const float* __restrict__ Wa,  const float* __restrict__ ba,
        const float* __restrict__ blo, int t, int hid_on) {
    extern __shared__ float s_x[];                 // 512*36 floats (logits)
    __shared__ __align__(16) float s_h[512];
    __shared__ __align__(16) float s_hl[512];
    __shared__ __align__(16) float s_he[512];
    __shared__ __align__(16) float s_v[512];
    __shared__ __align__(16) float s_red[512];
    __shared__ float s_sc[64], s_att[64];
    __shared__ unsigned long long s_bmax[32];
    int tid = threadIdx.x, lane = tid & 31, w = tid >> 5;

    if (blockIdx.x < 32) {
        // ---------------- hidden role: step t --------------------------------
        if (!hid_on) return;
        int b = blockIdx.x;
        int obuf = t & 1;

        // LSTM: fixed-order reduction of 16 partials + activation
        {
            int u = tid;
            float gi = b_ih[u]        + b_hh[u];
            float gf = b_ih[512 + u]  + b_hh[512 + u];
            float gg = b_ih[1024 + u] + b_hh[1024 + u];
            float go = b_ih[1536 + u] + b_hh[1536 + u];
            #pragma unroll
            for (int ks = 0; ks < KSG; ks++) {
                const float* gp = &g_gp[ks][b * 2048];
                gi += gp[u];
                gf += gp[512 + u];
                gg += gp[1024 + u];
                go += gp[1536 + u];
            }
            float si = 1.f / (1.f + expf(-gi));
            float sf = 1.f / (1.f + expf(-gf));
            float so = 1.f / (1.f + expf(-go));
            int idx = b * Hn + u;
            float c = sf * g_c[idx] + si * tanhf(gg);
            g_c[idx] = c;
            float h = so * tanhf(c);
            s_h[u] = h;
            g_h[idx] = h;
        }
        __syncthreads();

        gemv512_h(g_WhT,          blh, s_h,  s_red, s_hl, tid, 1);  // linear_hidden
        gemv512_h(g_WhT + 262144, beh, s_hl, s_red, s_he, tid, 0);  // embed_hidden

        for (int n = w; n < Nn; n += 16) {
            const float* fe = g_featemb + ((size_t)b * Nn + n) * Hn;
            float p = 0.f;
            #pragma unroll 8
            for (int h = lane; h < Hn; h += 32)
                p += Wa[h] * tanhf(fe[h] + s_he[h]);
            #pragma unroll
            for (int off = 16; off; off >>= 1)
                p += __shfl_xor_sync(0xffffffffu, p, off);
            if (lane == 0) s_sc[n] = p + ba[0];
        }
        __syncthreads();

        if (w == 0) {
            float v0 = (lane < Nn) ? s_sc[lane] : -1e30f;
            float v1 = (lane + 32 < Nn) ? s_sc[lane + 32] : -1e30f;
            float m = fmaxf(v0, v1);
            #pragma unroll
            for (int off = 16; off; off >>= 1)
                m = fmaxf(m, __shfl_xor_sync(0xffffffffu, m, off));
            float e0 = (lane < Nn) ? expf(v0 - m) : 0.f;
            float e1 = (lane + 32 < Nn) ? expf(v1 - m) : 0.f;
            float s = e0 + e1;
            #pragma unroll
            for (int off = 16; off; off >>= 1)
                s += __shfl_xor_sync(0xffffffffu, s, off);
            float inv = 1.f / s;
            if (lane < Nn) s_att[lane] = e0 * inv;
            if (lane + 32 < Nn) s_att[lane + 32] = e1 * inv;
        }
        __syncthreads();

        {
            int h = tid;
            float acc = s_hl[h];
            const float* fl = g_featlin + (size_t)b * Nn * Hn + h;
            #pragma unroll 10
            for (int n = 0; n < Nn; n++)
                acc += s_att[n] * fl[(size_t)n * Hn];
            s_v[h] = acc;
        }
        __syncthreads();

        gemv512_h(g_WhT + 524288, blo, s_v, s_red,
                  &g_voutb[obuf][b * Hn], tid, 1);                  // linear_out
    } else {
        // ---------------- logits role: step lt = t-1, 128 rows ---------------
        int lt = t - 1;
        if (lt < 0) return;
        int buf = lt & 1;
        int kq = tid >> 7;                 // 0..3 (128 k each)
        int rtid = tid & 127;              // row within tile
        int rowb = (blockIdx.x - 32) * 128;
        if (tid < 32) s_bmax[tid] = 0ull;

        for (int idx = tid; idx < 512 * Bn; idx += 512) {
            int b = idx >> 9, k = idx & 511;
            s_x[k * 36 + b] = g_voutb[buf][b * Hn + k];
        }
        __syncthreads();

        unsigned long long acc[16];
        #pragma unroll
        for (int i = 0; i < 16; i++) acc[i] = 0ull;

        const float* Wc = g_WoutT + (size_t)(kq * 128) * VOP + rowb + rtid;

        float wreg[8];
        #pragma unroll
        for (int j = 0; j < 8; j++) wreg[j] = Wc[(size_t)j * VOP];

        #pragma unroll 1
        for (int kt = 0; kt < 128; kt += 8) {
            float wcur[8];
            #pragma unroll
            for (int j = 0; j < 8; j++) wcur[j] = wreg[j];
            if (kt + 8 < 128) {
                #pragma unroll
                for (int j = 0; j < 8; j++) wreg[j] = Wc[(size_t)(kt + 8 + j) * VOP];
            }
            #pragma unroll
            for (int j = 0; j < 8; j++) {
                unsigned long long w2 = packf2(wcur[j], wcur[j]);
                const ulonglong2* x2 = (const ulonglong2*)&s_x[(kq * 128 + kt + j) * 36];
                #pragma unroll
                for (int q = 0; q < 8; q++) {
                    ulonglong2 xv = x2[q];
                    fma2(acc[2 * q], w2, xv.x);
                    fma2(acc[2 * q + 1], w2, xv.y);
                }
            }
        }

        // quarter combine (fixed order -> deterministic); reuse s_x area
        __syncthreads();
        float* red = s_x;                  // 3 * 128 * 33 = 12672 <= 18432
        if (kq) {
            float* dst = red + (size_t)(kq - 1) * 4224 + rtid * 33;
            #pragma unroll
            for (int a = 0; a < 16; a++) {
                float2 f = u2f2(acc[a]);
                dst[2 * a]     = f.x;
                dst[2 * a + 1] = f.y;
            }
        }
        __syncthreads();

        if (kq == 0) {
            const float* r1 = red + rtid * 33;
            const float* r2 = red + 4224 + rtid * 33;
            const float* r3 = red + 8448 + rtid * 33;
            int r = rowb + rtid;
            bool ok = r < VOn;
            float bo = ok ? bout[r] : 0.f;
            #pragma unroll
            for (int a = 0; a < 16; a++) {
                float2 f = u2f2(acc[a]);
                #pragma unroll
                for (int hh = 0; hh < 2; hh++) {
                    int b = 2 * a + hh;
                    float s = (hh ? f.y : f.x) + r1[b] + r2[b] + r3[b] + bo;
                    unsigned long long key = 0ull;
                    if (ok) {
                        __stcs(&out[((size_t)b * Tn + lt) * VOn + r], s);
                        unsigned u = __float_as_uint(s);
                        unsigned hi = (u & 0x80000000u) ? ~u : (u | 0x80000000u);
                        key = ((unsigned long long)hi << 32)
                            | (unsigned long long)(0x7FFFFFFFu - (unsigned)r);
                    }
                    #pragma unroll
                    for (int off = 16; off; off >>= 1) {
                        unsigned long long o2 = __shfl_xor_sync(0xffffffffu, key, off);
                        if (o2 > key) key = o2;
                    }
                    if (lane == 0) atomicMax(&s_bmax[b], key);
                }
            }
        }
        __syncthreads();
        if (tid < 32)
            atomicMax(&g_amax[tid * Tn + lt], s_bmax[tid]);
    }
}

// ---------------- convert argmax keys to float ids ---------------------------
__global__ void k_final(float* __restrict__ out_ids) {
    int i = blockIdx.x * blockDim.x + threadIdx.x;
    if (i >= Bn * Tn) return;
    unsigned long long key = g_amax[i];
    unsigned r = 0x7FFFFFFFu - (unsigned)(key & 0xFFFFFFFFull);
    out_ids[i] = (float)r;
}

// ---------------- launch ------------------------------------------------------
extern "C" void kernel_launch(void* const* d_in, const int* in_sizes, int n_in,
                              void* d_out, int out_size) {
    const float* features = (const float*)d_in[0];
    // d_in[1] = mask (unused)
    const int*   captions = (const int*)d_in[2];
    const float* table    = (const float*)d_in[3];
    const float* W_ih = (const float*)d_in[4];
    const float* b_ih = (const float*)d_in[5];
    const float* W_hh = (const float*)d_in[6];
    const float* b_hh = (const float*)d_in[7];
    const float* Wf  = (const float*)d_in[8];
    const float* bf  = (const float*)d_in[9];
    const float* We  = (const float*)d_in[10];
    const float* be  = (const float*)d_in[11];
    const float* Wlh = (const float*)d_in[12];
    const float* blh = (const float*)d_in[13];
    const float* Weh = (const float*)d_in[14];
    const float* beh = (const float*)d_in[15];
    const float* Wa  = (const float*)d_in[16];
    const float* ba  = (const float*)d_in[17];
    const float* Wlo = (const float*)d_in[18];
    const float* blo = (const float*)d_in[19];
    const float* Wout = (const float*)d_in[20];
    const float* bout = (const float*)d_in[21];
    float* out = (float*)d_out;

    cudaFuncSetAttribute(k_hidlog, cudaFuncAttributeMaxDynamicSharedMemorySize, SM_DYN);

    k_setup<<<6464, 256>>>(features, captions, table);
    k_tr<<<19840, dim3(32, 8)>>>(Wout, W_ih, W_hh, Wlh, Weh, Wlo);
    k_proj<<<dim3(Bn, Hn / 64), 256>>>(Wf, bf, features, 0);
    k_proj<<<dim3(Bn, Hn / 64), 256>>>(We, be, features, 1);

    for (int t = 0; t < Tn; t++) {
        k_gates<<<128, 256>>>(t);
        k_hidlog<<<282, 512, SM_DYN>>>(bout, out, b_ih, b_hh, blh, beh,
                                       Wa, ba, blo, t, 1);
    }
    k_hidlog<<<282, 512, SM_DYN>>>(bout, out, b_ih, b_hh, blh, beh,
                                   Wa, ba, blo, Tn, 0);   // final logits(99)

    float* ids = out + ((size_t)out_size - (size_t)Bn * Tn);
    k_final<<<(Bn * Tn + 255) / 256, 256>>>(ids);
}